// round 1
// baseline (speedup 1.0000x reference)
#include <cuda_runtime.h>
#include <math.h>

#define BB 2
#define SS 2048
#define EE 256
#define HH 32
#define DKK 8

// Intermediate attention output, [B, S, E] layout (h,d contiguous per token).
__device__ float g_attn[BB * SS * EE];

// ---------------------------------------------------------------------------
// Fused kernel: q = cos(x+theta); scores = q q^T / sqrt(dk); softmax; P @ q.
// One CTA handles one (b, h, query-chunk of 1024). All 2048 keys live in smem.
// No max-subtraction needed: |score| <= 8/sqrt(8) = 2.83 (exp safe).
// ---------------------------------------------------------------------------
__global__ __launch_bounds__(1024, 1) void attn_kernel(
    const float* __restrict__ x,
    const int*   __restrict__ mask,
    const float* __restrict__ theta)
{
    extern __shared__ float sm[];
    float* qs   = sm;             // [S * DK] = 2048*8 floats
    float* bias = sm + SS * DKK;  // [S]

    const int blk   = blockIdx.x;   // 128 blocks = b(2) * h(32) * chunk(2)
    const int chunk = blk & 1;
    const int bh    = blk >> 1;
    const int h     = bh & (HH - 1);
    const int b     = bh >> 5;
    const int tid   = threadIdx.x;

    // --- Fill qs = cos(x + theta) for this (b, h), all 2048 tokens ---
    const float* xb = x + (size_t)b * SS * EE + h * DKK;
    for (int i = tid; i < SS * DKK / 2; i += 1024) {
        int s  = i >> 2;
        int d2 = (i & 3) * 2;
        float2 v = *reinterpret_cast<const float2*>(xb + (size_t)s * EE + d2);
        float t0 = theta[d2];
        float t1 = theta[d2 + 1];
        qs[s * DKK + d2]     = cosf(v.x + t0);
        qs[s * DKK + d2 + 1] = cosf(v.y + t1);
    }
    // --- Mask bias ---
    const int* mrow = mask + (size_t)b * SS;
    for (int i = tid; i < SS; i += 1024)
        bias[i] = (mrow[i] != 0) ? 0.0f : -1e9f;
    __syncthreads();

    // --- Each thread owns one query row ---
    const int q0 = chunk * 1024 + tid;
    const float scale = 0.35355339059327373f;  // 1/sqrt(8)
    float qr[8];
#pragma unroll
    for (int d = 0; d < 8; d++) qr[d] = qs[q0 * 8 + d] * scale;

    float acc0 = 0.f, acc1 = 0.f, acc2 = 0.f, acc3 = 0.f;
    float acc4 = 0.f, acc5 = 0.f, acc6 = 0.f, acc7 = 0.f;
    float l = 0.f;

#pragma unroll 4
    for (int k = 0; k < SS; k++) {
        float4 ka = *reinterpret_cast<const float4*>(qs + k * 8);
        float4 kb = *reinterpret_cast<const float4*>(qs + k * 8 + 4);
        float s = bias[k];
        s = fmaf(qr[0], ka.x, s);
        s = fmaf(qr[1], ka.y, s);
        s = fmaf(qr[2], ka.z, s);
        s = fmaf(qr[3], ka.w, s);
        s = fmaf(qr[4], kb.x, s);
        s = fmaf(qr[5], kb.y, s);
        s = fmaf(qr[6], kb.z, s);
        s = fmaf(qr[7], kb.w, s);
        float p = __expf(s);
        l += p;
        acc0 = fmaf(p, ka.x, acc0);
        acc1 = fmaf(p, ka.y, acc1);
        acc2 = fmaf(p, ka.z, acc2);
        acc3 = fmaf(p, ka.w, acc3);
        acc4 = fmaf(p, kb.x, acc4);
        acc5 = fmaf(p, kb.y, acc5);
        acc6 = fmaf(p, kb.z, acc6);
        acc7 = fmaf(p, kb.w, acc7);
    }

    float inv = 1.0f / l;
    float* op = g_attn + (size_t)b * SS * EE + (size_t)q0 * EE + h * DKK;
    float4 o1 = make_float4(acc0 * inv, acc1 * inv, acc2 * inv, acc3 * inv);
    float4 o2 = make_float4(acc4 * inv, acc5 * inv, acc6 * inv, acc7 * inv);
    *reinterpret_cast<float4*>(op)     = o1;
    *reinterpret_cast<float4*>(op + 4) = o2;
}

// ---------------------------------------------------------------------------
// Output projection: Y[M=4096, 256] = A @ W^T + b
// Y[i,j] = sum_k A[i,k] * W[j,k] + b[j]
// 64x64 tile per CTA, K-tile 32, 256 threads, 4x4 micro-tile per thread.
// Both A and W tiles stored k-major in smem (transposed on store) so the
// inner loop is 2x LDS.128 + 16 FFMA per kk.
// ---------------------------------------------------------------------------
#define GM 64
#define GN 64
#define GK 32

__global__ __launch_bounds__(256, 4) void proj_kernel(
    const float* __restrict__ W,
    const float* __restrict__ bo,
    float*       __restrict__ Y)
{
    __shared__ float As[GK][GM + 4];  // [32][68] -> row stride 272B (16B aligned)
    __shared__ float Ws[GK][GN + 4];

    const float* A = g_attn;
    const int tid = threadIdx.x;
    const int im0 = blockIdx.x * GM;
    const int jn0 = blockIdx.y * GN;
    const int ty = tid >> 4;    // 0..15
    const int tx = tid & 15;    // 0..15

    float acc[4][4];
#pragma unroll
    for (int r = 0; r < 4; r++)
#pragma unroll
        for (int c = 0; c < 4; c++) acc[r][c] = 0.f;

    const int lrow = tid >> 3;        // 0..31
    const int lc4  = (tid & 7) * 4;   // k offset 0..28

    for (int k0 = 0; k0 < EE; k0 += GK) {
        // Load A tile (64 rows x 32 k), transpose into As[kk][row]
#pragma unroll
        for (int rr = 0; rr < 2; rr++) {
            int row = lrow + rr * 32;
            float4 v = *reinterpret_cast<const float4*>(
                A + (size_t)(im0 + row) * EE + k0 + lc4);
            As[lc4 + 0][row] = v.x;
            As[lc4 + 1][row] = v.y;
            As[lc4 + 2][row] = v.z;
            As[lc4 + 3][row] = v.w;
        }
        // Load W tile (64 j-rows x 32 k), transpose into Ws[kk][j]
#pragma unroll
        for (int rr = 0; rr < 2; rr++) {
            int row = lrow + rr * 32;
            float4 v = *reinterpret_cast<const float4*>(
                W + (size_t)(jn0 + row) * EE + k0 + lc4);
            Ws[lc4 + 0][row] = v.x;
            Ws[lc4 + 1][row] = v.y;
            Ws[lc4 + 2][row] = v.z;
            Ws[lc4 + 3][row] = v.w;
        }
        __syncthreads();

#pragma unroll
        for (int kk = 0; kk < GK; kk++) {
            float4 a4 = *reinterpret_cast<const float4*>(&As[kk][ty * 4]);
            float4 b4 = *reinterpret_cast<const float4*>(&Ws[kk][tx * 4]);
            acc[0][0] = fmaf(a4.x, b4.x, acc[0][0]);
            acc[0][1] = fmaf(a4.x, b4.y, acc[0][1]);
            acc[0][2] = fmaf(a4.x, b4.z, acc[0][2]);
            acc[0][3] = fmaf(a4.x, b4.w, acc[0][3]);
            acc[1][0] = fmaf(a4.y, b4.x, acc[1][0]);
            acc[1][1] = fmaf(a4.y, b4.y, acc[1][1]);
            acc[1][2] = fmaf(a4.y, b4.z, acc[1][2]);
            acc[1][3] = fmaf(a4.y, b4.w, acc[1][3]);
            acc[2][0] = fmaf(a4.z, b4.x, acc[2][0]);
            acc[2][1] = fmaf(a4.z, b4.y, acc[2][1]);
            acc[2][2] = fmaf(a4.z, b4.z, acc[2][2]);
            acc[2][3] = fmaf(a4.z, b4.w, acc[2][3]);
            acc[3][0] = fmaf(a4.w, b4.x, acc[3][0]);
            acc[3][1] = fmaf(a4.w, b4.y, acc[3][1]);
            acc[3][2] = fmaf(a4.w, b4.z, acc[3][2]);
            acc[3][3] = fmaf(a4.w, b4.w, acc[3][3]);
        }
        __syncthreads();
    }

    // Epilogue: add bias, vectorized stores
    float4 bv = *reinterpret_cast<const float4*>(bo + jn0 + tx * 4);
#pragma unroll
    for (int r = 0; r < 4; r++) {
        int i = im0 + ty * 4 + r;
        float4 o = make_float4(acc[r][0] + bv.x, acc[r][1] + bv.y,
                               acc[r][2] + bv.z, acc[r][3] + bv.w);
        *reinterpret_cast<float4*>(Y + (size_t)i * EE + jn0 + tx * 4) = o;
    }
}

// ---------------------------------------------------------------------------
extern "C" void kernel_launch(void* const* d_in, const int* in_sizes, int n_in,
                              void* d_out, int out_size)
{
    const float* x     = (const float*)d_in[0];
    const int*   mask  = (const int*)d_in[1];
    const float* theta = (const float*)d_in[2];
    const float* W     = (const float*)d_in[3];
    const float* bo    = (const float*)d_in[4];
    float*       out   = (float*)d_out;

    const size_t smem = (size_t)(SS * DKK + SS) * sizeof(float);  // 73728 B
    cudaFuncSetAttribute(attn_kernel,
                         cudaFuncAttributeMaxDynamicSharedMemorySize,
                         (int)smem);

    attn_kernel<<<BB * HH * 2, 1024, smem>>>(x, mask, theta);

    dim3 grid(BB * SS / GM, EE / GN);  // (64, 4)
    proj_kernel<<<grid, 256>>>(W, bo, out);
}

// round 2
// speedup vs baseline: 1.2352x; 1.2352x over previous
#include <cuda_runtime.h>
#include <math.h>
#include <stdint.h>

#define BB 2
#define SS 2048
#define EE 256
#define HH 32
#define DKK 8

// Intermediate attention output, [B, S, E] layout (h,d contiguous per token).
__device__ float g_attn[BB * SS * EE];

// ---- Blackwell f32x2 packed-math helpers (PTX-only; ptxas won't auto-fuse) ----
__device__ __forceinline__ uint64_t f2u(float x, float y) {
    uint64_t r;
    asm("mov.b64 %0, {%1,%2};" : "=l"(r) : "f"(x), "f"(y));
    return r;
}
__device__ __forceinline__ void u2f(uint64_t v, float& x, float& y) {
    asm("mov.b64 {%0,%1}, %2;" : "=f"(x), "=f"(y) : "l"(v));
}
__device__ __forceinline__ uint64_t ffma2(uint64_t a, uint64_t b, uint64_t c) {
    uint64_t d;
    asm("fma.rn.f32x2 %0, %1, %2, %3;" : "=l"(d) : "l"(a), "l"(b), "l"(c));
    return d;
}
__device__ __forceinline__ uint64_t fadd2(uint64_t a, uint64_t b) {
    uint64_t d;
    asm("add.rn.f32x2 %0, %1, %2;" : "=l"(d) : "l"(a), "l"(b));
    return d;
}
__device__ __forceinline__ float ex2(float x) {
    float r;
    asm("ex2.approx.ftz.f32 %0, %1;" : "=f"(r) : "f"(x));
    return r;
}

// log2(e) / sqrt(8): fold softmax temperature AND exp->exp2 conversion into q regs.
#define CSCALE 0.5100697279022178f

// ---------------------------------------------------------------------------
// Fused attention. One CTA = one (b, h, query-chunk of 1024). 512 threads,
// 2 queries per thread. Keys stored pair-interleaved in smem so key-pair
// operands load directly as packed f32x2 (LDS.128 -> 2x u64).
// No max-subtraction needed: |score*log2e| <= 4.1 (exp2 safe).
// ---------------------------------------------------------------------------
__global__ __launch_bounds__(512, 1) void attn_kernel(
    const float* __restrict__ x,
    const int*   __restrict__ mask,
    const float* __restrict__ theta)
{
    extern __shared__ float sm[];
    float*    kp    = sm;                                     // [1024][16] pair-interleaved keys
    uint64_t* bias2 = reinterpret_cast<uint64_t*>(sm + 1024 * 16);  // [1024] packed {b0,b1}

    const int blk   = blockIdx.x;   // 128 blocks = b(2) * h(32) * chunk(2)
    const int chunk = blk & 1;
    const int bh    = blk >> 1;
    const int h     = bh & (HH - 1);
    const int b     = bh >> 5;
    const int tid   = threadIdx.x;  // 0..511

    // --- Fill keys: kp[j][2*d + (s&1)] = cos(x[s][d] + theta[d]), j = s>>1 ---
    const float* xb = x + (size_t)b * SS * EE + h * DKK;
    for (int i = tid; i < SS * DKK / 2; i += 512) {
        int s  = i >> 2;
        int d2 = (i & 3) * 2;
        float2 v = *reinterpret_cast<const float2*>(xb + (size_t)s * EE + d2);
        float t0 = __ldg(theta + d2);
        float t1 = __ldg(theta + d2 + 1);
        int base = (s >> 1) * 16 + d2 * 2 + (s & 1);
        kp[base]     = cosf(v.x + t0);
        kp[base + 2] = cosf(v.y + t1);
    }
    // --- Mask bias (already in log2-exp domain: any huge negative works) ---
    const int* mrow = mask + (size_t)b * SS;
    for (int j = tid; j < SS / 2; j += 512) {
        int2 m = *reinterpret_cast<const int2*>(mrow + 2 * j);
        float b0 = (m.x != 0) ? 0.0f : -1e9f;
        float b1 = (m.y != 0) ? 0.0f : -1e9f;
        bias2[j] = f2u(b0, b1);
    }
    __syncthreads();

    // --- Each thread owns queries qa and qb; duplicate scaled q into f32x2 ---
    const int qa = chunk * 1024 + tid;
    const int qb = qa + 512;
    uint64_t qa2[8], qb2[8];
#pragma unroll
    for (int d = 0; d < 8; d++) {
        float va = kp[(qa >> 1) * 16 + 2 * d + (qa & 1)] * CSCALE;
        float vb = kp[(qb >> 1) * 16 + 2 * d + (qb & 1)] * CSCALE;
        qa2[d] = f2u(va, va);
        qb2[d] = f2u(vb, vb);
    }

    uint64_t accA[8], accB[8];
#pragma unroll
    for (int d = 0; d < 8; d++) { accA[d] = 0ull; accB[d] = 0ull; }
    uint64_t la = 0ull, lb = 0ull;
    const uint64_t zz = 0ull;

#pragma unroll 2
    for (int j = 0; j < SS / 2; j++) {
        const ulonglong2* k8 = reinterpret_cast<const ulonglong2*>(kp + j * 16);
        ulonglong2 v0 = k8[0];   // {k0[0],k1[0]} {k0[1],k1[1]}
        ulonglong2 v1 = k8[1];   // dims 2,3
        ulonglong2 v2 = k8[2];   // dims 4,5
        ulonglong2 v3 = k8[3];   // dims 6,7
        uint64_t bp = bias2[j];

        // dot products, split into two partial chains per query for ILP
        uint64_t saA = ffma2(qa2[0], v0.x, bp);
        uint64_t saB = ffma2(qa2[4], v2.x, zz);
        uint64_t sbA = ffma2(qb2[0], v0.x, bp);
        uint64_t sbB = ffma2(qb2[4], v2.x, zz);
        saA = ffma2(qa2[1], v0.y, saA);  saB = ffma2(qa2[5], v2.y, saB);
        sbA = ffma2(qb2[1], v0.y, sbA);  sbB = ffma2(qb2[5], v2.y, sbB);
        saA = ffma2(qa2[2], v1.x, saA);  saB = ffma2(qa2[6], v3.x, saB);
        sbA = ffma2(qb2[2], v1.x, sbA);  sbB = ffma2(qb2[6], v3.x, sbB);
        saA = ffma2(qa2[3], v1.y, saA);  saB = ffma2(qa2[7], v3.y, saB);
        sbA = ffma2(qb2[3], v1.y, sbA);  sbB = ffma2(qb2[7], v3.y, sbB);
        uint64_t sa = fadd2(saA, saB);
        uint64_t sb = fadd2(sbA, sbB);

        float sa0, sa1, sb0, sb1;
        u2f(sa, sa0, sa1);
        u2f(sb, sb0, sb1);
        uint64_t pa = f2u(ex2(sa0), ex2(sa1));
        uint64_t pb = f2u(ex2(sb0), ex2(sb1));
        la = fadd2(la, pa);
        lb = fadd2(lb, pb);

        accA[0] = ffma2(pa, v0.x, accA[0]);  accB[0] = ffma2(pb, v0.x, accB[0]);
        accA[1] = ffma2(pa, v0.y, accA[1]);  accB[1] = ffma2(pb, v0.y, accB[1]);
        accA[2] = ffma2(pa, v1.x, accA[2]);  accB[2] = ffma2(pb, v1.x, accB[2]);
        accA[3] = ffma2(pa, v1.y, accA[3]);  accB[3] = ffma2(pb, v1.y, accB[3]);
        accA[4] = ffma2(pa, v2.x, accA[4]);  accB[4] = ffma2(pb, v2.x, accB[4]);
        accA[5] = ffma2(pa, v2.y, accA[5]);  accB[5] = ffma2(pb, v2.y, accB[5]);
        accA[6] = ffma2(pa, v3.x, accA[6]);  accB[6] = ffma2(pb, v3.x, accB[6]);
        accA[7] = ffma2(pa, v3.y, accA[7]);  accB[7] = ffma2(pb, v3.y, accB[7]);
    }

    // --- Reduce packed halves, normalize, store both query rows ---
    float lx, ly;
    u2f(la, lx, ly);
    float inva = 1.0f / (lx + ly);
    u2f(lb, lx, ly);
    float invb = 1.0f / (lx + ly);

    float oa[8], ob[8];
#pragma unroll
    for (int d = 0; d < 8; d++) {
        float x0, x1;
        u2f(accA[d], x0, x1);  oa[d] = (x0 + x1) * inva;
        u2f(accB[d], x0, x1);  ob[d] = (x0 + x1) * invb;
    }

    float* opa = g_attn + (size_t)b * SS * EE + (size_t)qa * EE + h * DKK;
    float* opb = g_attn + (size_t)b * SS * EE + (size_t)qb * EE + h * DKK;
    *reinterpret_cast<float4*>(opa)     = make_float4(oa[0], oa[1], oa[2], oa[3]);
    *reinterpret_cast<float4*>(opa + 4) = make_float4(oa[4], oa[5], oa[6], oa[7]);
    *reinterpret_cast<float4*>(opb)     = make_float4(ob[0], ob[1], ob[2], ob[3]);
    *reinterpret_cast<float4*>(opb + 4) = make_float4(ob[4], ob[5], ob[6], ob[7]);
}

// ---------------------------------------------------------------------------
// Output projection: Y[M=4096, 256] = A @ W^T + b   (unchanged from R1)
// ---------------------------------------------------------------------------
#define GM 64
#define GN 64
#define GK 32

__global__ __launch_bounds__(256, 4) void proj_kernel(
    const float* __restrict__ W,
    const float* __restrict__ bo,
    float*       __restrict__ Y)
{
    __shared__ float As[GK][GM + 4];
    __shared__ float Ws[GK][GN + 4];

    const float* A = g_attn;
    const int tid = threadIdx.x;
    const int im0 = blockIdx.x * GM;
    const int jn0 = blockIdx.y * GN;
    const int ty = tid >> 4;
    const int tx = tid & 15;

    float acc[4][4];
#pragma unroll
    for (int r = 0; r < 4; r++)
#pragma unroll
        for (int c = 0; c < 4; c++) acc[r][c] = 0.f;

    const int lrow = tid >> 3;
    const int lc4  = (tid & 7) * 4;

    for (int k0 = 0; k0 < EE; k0 += GK) {
#pragma unroll
        for (int rr = 0; rr < 2; rr++) {
            int row = lrow + rr * 32;
            float4 v = *reinterpret_cast<const float4*>(
                A + (size_t)(im0 + row) * EE + k0 + lc4);
            As[lc4 + 0][row] = v.x;
            As[lc4 + 1][row] = v.y;
            As[lc4 + 2][row] = v.z;
            As[lc4 + 3][row] = v.w;
        }
#pragma unroll
        for (int rr = 0; rr < 2; rr++) {
            int row = lrow + rr * 32;
            float4 v = *reinterpret_cast<const float4*>(
                W + (size_t)(jn0 + row) * EE + k0 + lc4);
            Ws[lc4 + 0][row] = v.x;
            Ws[lc4 + 1][row] = v.y;
            Ws[lc4 + 2][row] = v.z;
            Ws[lc4 + 3][row] = v.w;
        }
        __syncthreads();

#pragma unroll
        for (int kk = 0; kk < GK; kk++) {
            float4 a4 = *reinterpret_cast<const float4*>(&As[kk][ty * 4]);
            float4 b4 = *reinterpret_cast<const float4*>(&Ws[kk][tx * 4]);
            acc[0][0] = fmaf(a4.x, b4.x, acc[0][0]);
            acc[0][1] = fmaf(a4.x, b4.y, acc[0][1]);
            acc[0][2] = fmaf(a4.x, b4.z, acc[0][2]);
            acc[0][3] = fmaf(a4.x, b4.w, acc[0][3]);
            acc[1][0] = fmaf(a4.y, b4.x, acc[1][0]);
            acc[1][1] = fmaf(a4.y, b4.y, acc[1][1]);
            acc[1][2] = fmaf(a4.y, b4.z, acc[1][2]);
            acc[1][3] = fmaf(a4.y, b4.w, acc[1][3]);
            acc[2][0] = fmaf(a4.z, b4.x, acc[2][0]);
            acc[2][1] = fmaf(a4.z, b4.y, acc[2][1]);
            acc[2][2] = fmaf(a4.z, b4.z, acc[2][2]);
            acc[2][3] = fmaf(a4.z, b4.w, acc[2][3]);
            acc[3][0] = fmaf(a4.w, b4.x, acc[3][0]);
            acc[3][1] = fmaf(a4.w, b4.y, acc[3][1]);
            acc[3][2] = fmaf(a4.w, b4.z, acc[3][2]);
            acc[3][3] = fmaf(a4.w, b4.w, acc[3][3]);
        }
        __syncthreads();
    }

    float4 bv = *reinterpret_cast<const float4*>(bo + jn0 + tx * 4);
#pragma unroll
    for (int r = 0; r < 4; r++) {
        int i = im0 + ty * 4 + r;
        float4 o = make_float4(acc[r][0] + bv.x, acc[r][1] + bv.y,
                               acc[r][2] + bv.z, acc[r][3] + bv.w);
        *reinterpret_cast<float4*>(Y + (size_t)i * EE + jn0 + tx * 4) = o;
    }
}

// ---------------------------------------------------------------------------
extern "C" void kernel_launch(void* const* d_in, const int* in_sizes, int n_in,
                              void* d_out, int out_size)
{
    const float* x     = (const float*)d_in[0];
    const int*   mask  = (const int*)d_in[1];
    const float* theta = (const float*)d_in[2];
    const float* W     = (const float*)d_in[3];
    const float* bo    = (const float*)d_in[4];
    float*       out   = (float*)d_out;

    const size_t smem = (size_t)(SS * DKK + SS) * sizeof(float);  // 73728 B
    cudaFuncSetAttribute(attn_kernel,
                         cudaFuncAttributeMaxDynamicSharedMemorySize,
                         (int)smem);

    attn_kernel<<<BB * HH * 2, 512, smem>>>(x, mask, theta);

    dim3 grid(BB * SS / GM, EE / GN);  // (64, 4)
    proj_kernel<<<grid, 256>>>(W, bo, out);
}

// round 3
// speedup vs baseline: 1.2361x; 1.0007x over previous
#include <cuda_runtime.h>
#include <math.h>
#include <stdint.h>

#define BB 2
#define SS 2048
#define EE 256
#define HH 32
#define DKK 8

// Intermediate attention output, [B, S, E] layout (h,d contiguous per token).
__device__ float g_attn[BB * SS * EE];

// ---- Blackwell f32x2 packed-math helpers (PTX-only; ptxas won't auto-fuse) ----
__device__ __forceinline__ uint64_t f2u(float x, float y) {
    uint64_t r;
    asm("mov.b64 %0, {%1,%2};" : "=l"(r) : "f"(x), "f"(y));
    return r;
}
__device__ __forceinline__ void u2f(uint64_t v, float& x, float& y) {
    asm("mov.b64 {%0,%1}, %2;" : "=f"(x), "=f"(y) : "l"(v));
}
__device__ __forceinline__ uint64_t ffma2(uint64_t a, uint64_t b, uint64_t c) {
    uint64_t d;
    asm("fma.rn.f32x2 %0, %1, %2, %3;" : "=l"(d) : "l"(a), "l"(b), "l"(c));
    return d;
}
__device__ __forceinline__ uint64_t fadd2(uint64_t a, uint64_t b) {
    uint64_t d;
    asm("add.rn.f32x2 %0, %1, %2;" : "=l"(d) : "l"(a), "l"(b));
    return d;
}
__device__ __forceinline__ float ex2(float x) {
    float r;
    asm("ex2.approx.ftz.f32 %0, %1;" : "=f"(r) : "f"(x));
    return r;
}

// log2(e) / sqrt(8): fold softmax temperature AND exp->exp2 conversion into q regs.
#define CSCALE 0.5100697279022178f

// ---------------------------------------------------------------------------
// Fused attention. One CTA = one (b, h, query-chunk of 1024). 512 threads,
// 2 queries per thread. Keys stored pair-interleaved in smem so key-pair
// operands load directly as packed f32x2 (LDS.128 -> 2x u64).
// No max-subtraction needed: |score*log2e| <= 4.1 (exp2 safe).
// ---------------------------------------------------------------------------
__global__ __launch_bounds__(512, 1) void attn_kernel(
    const float* __restrict__ x,
    const int*   __restrict__ mask,
    const float* __restrict__ theta)
{
    extern __shared__ float sm[];
    float*    kp    = sm;                                     // [1024][16] pair-interleaved keys
    uint64_t* bias2 = reinterpret_cast<uint64_t*>(sm + 1024 * 16);  // [1024] packed {b0,b1}

    const int blk   = blockIdx.x;   // 128 blocks = b(2) * h(32) * chunk(2)
    const int chunk = blk & 1;
    const int bh    = blk >> 1;
    const int h     = bh & (HH - 1);
    const int b     = bh >> 5;
    const int tid   = threadIdx.x;  // 0..511

    // --- Fill keys: kp[j][2*d + (s&1)] = cos(x[s][d] + theta[d]), j = s>>1 ---
    const float* xb = x + (size_t)b * SS * EE + h * DKK;
    for (int i = tid; i < SS * DKK / 2; i += 512) {
        int s  = i >> 2;
        int d2 = (i & 3) * 2;
        float2 v = *reinterpret_cast<const float2*>(xb + (size_t)s * EE + d2);
        float t0 = __ldg(theta + d2);
        float t1 = __ldg(theta + d2 + 1);
        int base = (s >> 1) * 16 + d2 * 2 + (s & 1);
        kp[base]     = cosf(v.x + t0);
        kp[base + 2] = cosf(v.y + t1);
    }
    // --- Mask bias (already in log2-exp domain: any huge negative works) ---
    const int* mrow = mask + (size_t)b * SS;
    for (int j = tid; j < SS / 2; j += 512) {
        int2 m = *reinterpret_cast<const int2*>(mrow + 2 * j);
        float b0 = (m.x != 0) ? 0.0f : -1e9f;
        float b1 = (m.y != 0) ? 0.0f : -1e9f;
        bias2[j] = f2u(b0, b1);
    }
    __syncthreads();

    // --- Each thread owns queries qa and qb; duplicate scaled q into f32x2 ---
    const int qa = chunk * 1024 + tid;
    const int qb = qa + 512;
    uint64_t qa2[8], qb2[8];
#pragma unroll
    for (int d = 0; d < 8; d++) {
        float va = kp[(qa >> 1) * 16 + 2 * d + (qa & 1)] * CSCALE;
        float vb = kp[(qb >> 1) * 16 + 2 * d + (qb & 1)] * CSCALE;
        qa2[d] = f2u(va, va);
        qb2[d] = f2u(vb, vb);
    }

    uint64_t accA[8], accB[8];
#pragma unroll
    for (int d = 0; d < 8; d++) { accA[d] = 0ull; accB[d] = 0ull; }
    uint64_t la = 0ull, lb = 0ull;
    const uint64_t zz = 0ull;

#pragma unroll 2
    for (int j = 0; j < SS / 2; j++) {
        const ulonglong2* k8 = reinterpret_cast<const ulonglong2*>(kp + j * 16);
        ulonglong2 v0 = k8[0];   // {k0[0],k1[0]} {k0[1],k1[1]}
        ulonglong2 v1 = k8[1];   // dims 2,3
        ulonglong2 v2 = k8[2];   // dims 4,5
        ulonglong2 v3 = k8[3];   // dims 6,7
        uint64_t bp = bias2[j];

        // dot products, split into two partial chains per query for ILP
        uint64_t saA = ffma2(qa2[0], v0.x, bp);
        uint64_t saB = ffma2(qa2[4], v2.x, zz);
        uint64_t sbA = ffma2(qb2[0], v0.x, bp);
        uint64_t sbB = ffma2(qb2[4], v2.x, zz);
        saA = ffma2(qa2[1], v0.y, saA);  saB = ffma2(qa2[5], v2.y, saB);
        sbA = ffma2(qb2[1], v0.y, sbA);  sbB = ffma2(qb2[5], v2.y, sbB);
        saA = ffma2(qa2[2], v1.x, saA);  saB = ffma2(qa2[6], v3.x, saB);
        sbA = ffma2(qb2[2], v1.x, sbA);  sbB = ffma2(qb2[6], v3.x, sbB);
        saA = ffma2(qa2[3], v1.y, saA);  saB = ffma2(qa2[7], v3.y, saB);
        sbA = ffma2(qb2[3], v1.y, sbA);  sbB = ffma2(qb2[7], v3.y, sbB);
        uint64_t sa = fadd2(saA, saB);
        uint64_t sb = fadd2(sbA, sbB);

        float sa0, sa1, sb0, sb1;
        u2f(sa, sa0, sa1);
        u2f(sb, sb0, sb1);
        uint64_t pa = f2u(ex2(sa0), ex2(sa1));
        uint64_t pb = f2u(ex2(sb0), ex2(sb1));
        la = fadd2(la, pa);
        lb = fadd2(lb, pb);

        accA[0] = ffma2(pa, v0.x, accA[0]);  accB[0] = ffma2(pb, v0.x, accB[0]);
        accA[1] = ffma2(pa, v0.y, accA[1]);  accB[1] = ffma2(pb, v0.y, accB[1]);
        accA[2] = ffma2(pa, v1.x, accA[2]);  accB[2] = ffma2(pb, v1.x, accB[2]);
        accA[3] = ffma2(pa, v1.y, accA[3]);  accB[3] = ffma2(pb, v1.y, accB[3]);
        accA[4] = ffma2(pa, v2.x, accA[4]);  accB[4] = ffma2(pb, v2.x, accB[4]);
        accA[5] = ffma2(pa, v2.y, accA[5]);  accB[5] = ffma2(pb, v2.y, accB[5]);
        accA[6] = ffma2(pa, v3.x, accA[6]);  accB[6] = ffma2(pb, v3.x, accB[6]);
        accA[7] = ffma2(pa, v3.y, accA[7]);  accB[7] = ffma2(pb, v3.y, accB[7]);
    }

    // --- Reduce packed halves, normalize, store both query rows ---
    float lx, ly;
    u2f(la, lx, ly);
    float inva = 1.0f / (lx + ly);
    u2f(lb, lx, ly);
    float invb = 1.0f / (lx + ly);

    float oa[8], ob[8];
#pragma unroll
    for (int d = 0; d < 8; d++) {
        float x0, x1;
        u2f(accA[d], x0, x1);  oa[d] = (x0 + x1) * inva;
        u2f(accB[d], x0, x1);  ob[d] = (x0 + x1) * invb;
    }

    float* opa = g_attn + (size_t)b * SS * EE + (size_t)qa * EE + h * DKK;
    float* opb = g_attn + (size_t)b * SS * EE + (size_t)qb * EE + h * DKK;
    *reinterpret_cast<float4*>(opa)     = make_float4(oa[0], oa[1], oa[2], oa[3]);
    *reinterpret_cast<float4*>(opa + 4) = make_float4(oa[4], oa[5], oa[6], oa[7]);
    *reinterpret_cast<float4*>(opb)     = make_float4(ob[0], ob[1], ob[2], ob[3]);
    *reinterpret_cast<float4*>(opb + 4) = make_float4(ob[4], ob[5], ob[6], ob[7]);
}

// ---------------------------------------------------------------------------
// Output projection: Y[M=4096, 256] = A @ W^T + b   (unchanged from R1)
// ---------------------------------------------------------------------------
#define GM 64
#define GN 64
#define GK 32

__global__ __launch_bounds__(256, 4) void proj_kernel(
    const float* __restrict__ W,
    const float* __restrict__ bo,
    float*       __restrict__ Y)
{
    __shared__ float As[GK][GM + 4];
    __shared__ float Ws[GK][GN + 4];

    const float* A = g_attn;
    const int tid = threadIdx.x;
    const int im0 = blockIdx.x * GM;
    const int jn0 = blockIdx.y * GN;
    const int ty = tid >> 4;
    const int tx = tid & 15;

    float acc[4][4];
#pragma unroll
    for (int r = 0; r < 4; r++)
#pragma unroll
        for (int c = 0; c < 4; c++) acc[r][c] = 0.f;

    const int lrow = tid >> 3;
    const int lc4  = (tid & 7) * 4;

    for (int k0 = 0; k0 < EE; k0 += GK) {
#pragma unroll
        for (int rr = 0; rr < 2; rr++) {
            int row = lrow + rr * 32;
            float4 v = *reinterpret_cast<const float4*>(
                A + (size_t)(im0 + row) * EE + k0 + lc4);
            As[lc4 + 0][row] = v.x;
            As[lc4 + 1][row] = v.y;
            As[lc4 + 2][row] = v.z;
            As[lc4 + 3][row] = v.w;
        }
#pragma unroll
        for (int rr = 0; rr < 2; rr++) {
            int row = lrow + rr * 32;
            float4 v = *reinterpret_cast<const float4*>(
                W + (size_t)(jn0 + row) * EE + k0 + lc4);
            Ws[lc4 + 0][row] = v.x;
            Ws[lc4 + 1][row] = v.y;
            Ws[lc4 + 2][row] = v.z;
            Ws[lc4 + 3][row] = v.w;
        }
        __syncthreads();

#pragma unroll
        for (int kk = 0; kk < GK; kk++) {
            float4 a4 = *reinterpret_cast<const float4*>(&As[kk][ty * 4]);
            float4 b4 = *reinterpret_cast<const float4*>(&Ws[kk][tx * 4]);
            acc[0][0] = fmaf(a4.x, b4.x, acc[0][0]);
            acc[0][1] = fmaf(a4.x, b4.y, acc[0][1]);
            acc[0][2] = fmaf(a4.x, b4.z, acc[0][2]);
            acc[0][3] = fmaf(a4.x, b4.w, acc[0][3]);
            acc[1][0] = fmaf(a4.y, b4.x, acc[1][0]);
            acc[1][1] = fmaf(a4.y, b4.y, acc[1][1]);
            acc[1][2] = fmaf(a4.y, b4.z, acc[1][2]);
            acc[1][3] = fmaf(a4.y, b4.w, acc[1][3]);
            acc[2][0] = fmaf(a4.z, b4.x, acc[2][0]);
            acc[2][1] = fmaf(a4.z, b4.y, acc[2][1]);
            acc[2][2] = fmaf(a4.z, b4.z, acc[2][2]);
            acc[2][3] = fmaf(a4.z, b4.w, acc[2][3]);
            acc[3][0] = fmaf(a4.w, b4.x, acc[3][0]);
            acc[3][1] = fmaf(a4.w, b4.y, acc[3][1]);
            acc[3][2] = fmaf(a4.w, b4.z, acc[3][2]);
            acc[3][3] = fmaf(a4.w, b4.w, acc[3][3]);
        }
        __syncthreads();
    }

    float4 bv = *reinterpret_cast<const float4*>(bo + jn0 + tx * 4);
#pragma unroll
    for (int r = 0; r < 4; r++) {
        int i = im0 + ty * 4 + r;
        float4 o = make_float4(acc[r][0] + bv.x, acc[r][1] + bv.y,
                               acc[r][2] + bv.z, acc[r][3] + bv.w);
        *reinterpret_cast<float4*>(Y + (size_t)i * EE + jn0 + tx * 4) = o;
    }
}

// ---------------------------------------------------------------------------
extern "C" void kernel_launch(void* const* d_in, const int* in_sizes, int n_in,
                              void* d_out, int out_size)
{
    const float* x     = (const float*)d_in[0];
    const int*   mask  = (const int*)d_in[1];
    const float* theta = (const float*)d_in[2];
    const float* W     = (const float*)d_in[3];
    const float* bo    = (const float*)d_in[4];
    float*       out   = (float*)d_out;

    const size_t smem = (size_t)(SS * DKK + SS) * sizeof(float);  // 73728 B
    cudaFuncSetAttribute(attn_kernel,
                         cudaFuncAttributeMaxDynamicSharedMemorySize,
                         (int)smem);

    attn_kernel<<<BB * HH * 2, 512, smem>>>(x, mask, theta);

    dim3 grid(BB * SS / GM, EE / GN);  // (64, 4)
    proj_kernel<<<grid, 256>>>(W, bo, out);
}

// round 6
// speedup vs baseline: 2.4079x; 1.9480x over previous
#include <cuda_runtime.h>
#include <cuda_bf16.h>
#include <math.h>
#include <stdint.h>

#define BB 2
#define SS 2048
#define EE 256
#define HH 32

// log2(e)/sqrt(8): fold softmax temperature + exp->exp2 into one scale.
#define CSCALE 0.51006972790221780093f

__device__ float g_attn[BB * SS * EE];   // attention output [B,S,E]
__device__ uint4 g_qhi[64 * 2048];       // bf16 hi of cos(x+theta): 8 vals (16B) per (bh,s)
__device__ uint4 g_qlo[64 * 2048];       // bf16 lo residual

__device__ __forceinline__ float ex2f(float x) {
    float r;
    asm("ex2.approx.ftz.f32 %0, %1;" : "=f"(r) : "f"(x));
    return r;
}
__device__ __forceinline__ float bf16lo(uint32_t u) {
    return __uint_as_float(u << 16);
}
__device__ __forceinline__ float bf16hi(uint32_t u) {
    return __uint_as_float(u & 0xFFFF0000u);
}
// Warp-level bf16 MMA, D/C fp32. Baseline sm_80 PTX -> compiles for compute_103.
__device__ __forceinline__ void mma16816(float d[4],
    uint32_t a0, uint32_t a1, uint32_t a2, uint32_t a3,
    uint32_t b0, uint32_t b1, const float c[4])
{
    asm volatile("mma.sync.aligned.m16n8k16.row.col.f32.bf16.bf16.f32 "
        "{%0,%1,%2,%3}, {%4,%5,%6,%7}, {%8,%9}, {%10,%11,%12,%13};"
        : "=f"(d[0]), "=f"(d[1]), "=f"(d[2]), "=f"(d[3])
        : "r"(a0), "r"(a1), "r"(a2), "r"(a3), "r"(b0), "r"(b1),
          "f"(c[0]), "f"(c[1]), "f"(c[2]), "f"(c[3]));
}

// ---------------------------------------------------------------------------
// Prep: q = cos(x + theta) -> bf16 hi + bf16 lo residual, layout [bh][s] x 16B
// ---------------------------------------------------------------------------
__global__ void prep_kernel(const float* __restrict__ x,
                            const float* __restrict__ theta)
{
    int idx = blockIdx.x * 256 + threadIdx.x;  // 0 .. 64*2048-1
    int bh = idx >> 11;
    int s  = idx & 2047;
    int b  = bh >> 5;
    int h  = bh & 31;
    const float* xr = x + ((size_t)b * SS + s) * EE + h * 8;
    float4 v0 = *reinterpret_cast<const float4*>(xr);
    float4 v1 = *reinterpret_cast<const float4*>(xr + 4);
    float v[8] = {v0.x, v0.y, v0.z, v0.w, v1.x, v1.y, v1.z, v1.w};
    unsigned short hs[8], ls[8];
#pragma unroll
    for (int d = 0; d < 8; d++) {
        float cv = cosf(v[d] + __ldg(theta + d));
        __nv_bfloat16 hb = __float2bfloat16(cv);
        float rem = cv - __bfloat162float(hb);
        __nv_bfloat16 lb = __float2bfloat16(rem);
        hs[d] = *reinterpret_cast<unsigned short*>(&hb);
        ls[d] = *reinterpret_cast<unsigned short*>(&lb);
    }
    uint4 H, L;
    H.x = hs[0] | (uint32_t)hs[1] << 16;  H.y = hs[2] | (uint32_t)hs[3] << 16;
    H.z = hs[4] | (uint32_t)hs[5] << 16;  H.w = hs[6] | (uint32_t)hs[7] << 16;
    L.x = ls[0] | (uint32_t)ls[1] << 16;  L.y = ls[2] | (uint32_t)ls[3] << 16;
    L.z = ls[4] | (uint32_t)ls[5] << 16;  L.w = ls[6] | (uint32_t)ls[7] << 16;
    g_qhi[idx] = H;
    g_qlo[idx] = L;
}

// ---------------------------------------------------------------------------
// Warp-MMA flash attention. CTA = (bh, 128-query tile); 8 warps x 16 queries.
// S = Qhi*Khi + Qhi*Klo + Qlo*Khi + bias  (2 bf16 MMAs, fp32-grade scores)
// P = exp2(S*CSCALE), bf16-rounded in registers -> A-fragment of the PV MMA.
// Denominator accumulates the SAME bf16-rounded p values (common-mode cancel).
// ---------------------------------------------------------------------------
__global__ __launch_bounds__(256, 2) void attn_kernel(const int* __restrict__ mask)
{
    __shared__ uint4    sKhi[128];       // K hi tile, 16B per key
    __shared__ uint4    sKlo[128];       // K lo tile
    __shared__ uint32_t sBias[128];      // {bf16 bias, 0} packed per key
    __shared__ uint32_t sVT[8][68];      // V^T [dim][key-pair u32], padded stride 68

    const int tid  = threadIdx.x;
    const int wid  = tid >> 5;
    const int lane = tid & 31;
    const int r = lane >> 2;             // fragment row / B-col index
    const int m = lane & 3;              // fragment k-group index
    const int bh = blockIdx.x >> 4;
    const int qt = blockIdx.x & 15;
    const int b  = bh >> 5;

    // --- Fixed A fragments (this warp's 16 queries) ---
    const int qbase = (bh << 11) + (qt << 7) + wid * 16;
    const uint32_t* qhw = reinterpret_cast<const uint32_t*>(g_qhi + qbase);
    const uint32_t* qlw = reinterpret_cast<const uint32_t*>(g_qlo + qbase);
    uint32_t A1[4], A2[4];
    A1[0] = qhw[r * 4 + m];              // row r,   dims 2m,2m+1
    A1[1] = qhw[(r + 8) * 4 + m];        // row r+8
    A1[2] = A1[0];                       // cols 8-15 duplicate Qhi (x Klo rows)
    A1[3] = A1[1];
    A2[0] = qlw[r * 4 + m];
    A2[1] = qlw[(r + 8) * 4 + m];
    A2[2] = (m == 0) ? 0x3F80u : 0u;     // e0 column: 1.0 at col 8 -> picks bias row
    A2[3] = A2[2];

    float O[4] = {0.f, 0.f, 0.f, 0.f};   // output fragment [16q x 8d]
    float l_lo = 0.f, l_hi = 0.f;        // softmax denominators (rows r, r+8)

    const uint32_t* khi32 = reinterpret_cast<const uint32_t*>(sKhi);
    const uint32_t* klo32 = reinterpret_cast<const uint32_t*>(sKlo);

    for (int c = 0; c < 16; c++) {
        __syncthreads();                 // previous chunk's reads complete
        const int kg = (bh << 11) + (c << 7);
        if (tid < 128) {
            sKhi[tid] = g_qhi[kg + tid];
            int mk = mask[b * SS + (c << 7) + tid];
            sBias[tid] = mk ? 0u : 0xC2C8u;          // bf16(-100) in low half
        } else {
            sKlo[tid - 128] = g_qlo[kg + tid - 128]; // FULL 128 keys
        }
        if (tid >= 192) {
            int u = tid - 192;                        // keys 2u, 2u+1
            uint4 a  = g_qhi[kg + 2 * u];
            uint4 bq = g_qhi[kg + 2 * u + 1];
            uint32_t ua[4] = {a.x, a.y, a.z, a.w};
            uint32_t ub[4] = {bq.x, bq.y, bq.z, bq.w};
#pragma unroll
            for (int d = 0; d < 8; d++) {
                uint32_t sel = (d & 1) ? 0x7632u : 0x5410u;
                sVT[d][u] = __byte_perm(ua[d >> 1], ub[d >> 1], sel);
            }
        }
        __syncthreads();

        // --- S = QK^T + bias over 128 keys; exp2 + bf16 round in registers ---
        uint32_t P[16][2];
#pragma unroll
        for (int j = 0; j < 16; j++) {
            int key = 8 * j + r;
            uint32_t b1l = khi32[key * 4 + m];        // Khi dims 2m,2m+1
            uint32_t b1h = klo32[key * 4 + m];        // Klo (rows 8-15)
            uint32_t b2h = (m == 0) ? sBias[key] : 0u;
            float D[4] = {0.f, 0.f, 0.f, 0.f};
            mma16816(D, A1[0], A1[1], A1[2], A1[3], b1l, b1h, D);
            mma16816(D, A2[0], A2[1], A2[2], A2[3], b1l, b2h, D);
            float p0 = ex2f(D[0] * CSCALE);
            float p1 = ex2f(D[1] * CSCALE);
            float p2 = ex2f(D[2] * CSCALE);
            float p3 = ex2f(D[3] * CSCALE);
            uint32_t pkA, pkB;
            asm("cvt.rn.bf16x2.f32 %0, %1, %2;" : "=r"(pkA) : "f"(p1), "f"(p0));
            asm("cvt.rn.bf16x2.f32 %0, %1, %2;" : "=r"(pkB) : "f"(p3), "f"(p2));
            P[j][0] = pkA;
            P[j][1] = pkB;
            // denominator from the SAME bf16-rounded values (consistency)
            l_lo += bf16lo(pkA) + bf16hi(pkA);
            l_hi += bf16lo(pkB) + bf16hi(pkB);
        }

        // --- O += P * V  (8 k16 steps over 128 keys) ---
#pragma unroll
        for (int t = 0; t < 8; t++) {
            uint32_t b0 = sVT[r][t * 8 + m];          // keys 16t+2m, +1  (dim r)
            uint32_t b1 = sVT[r][t * 8 + 4 + m];      // keys 16t+8+2m, +1
            mma16816(O, P[2 * t][0], P[2 * t][1], P[2 * t + 1][0], P[2 * t + 1][1],
                     b0, b1, O);
        }
    }

    // --- Reduce denominators across the 4 threads sharing each row ---
    l_lo += __shfl_xor_sync(0xffffffffu, l_lo, 1);
    l_lo += __shfl_xor_sync(0xffffffffu, l_lo, 2);
    l_hi += __shfl_xor_sync(0xffffffffu, l_hi, 1);
    l_hi += __shfl_xor_sync(0xffffffffu, l_hi, 2);
    float inv_lo = 1.0f / l_lo;
    float inv_hi = 1.0f / l_hi;

    const int h  = bh & 31;
    const int q0 = (qt << 7) + wid * 16 + r;
    float* o1 = g_attn + ((size_t)b * SS + q0) * EE + h * 8 + 2 * m;
    float* o2 = o1 + 8 * EE;
    *reinterpret_cast<float2*>(o1) = make_float2(O[0] * inv_lo, O[1] * inv_lo);
    *reinterpret_cast<float2*>(o2) = make_float2(O[2] * inv_hi, O[3] * inv_hi);
}

// ---------------------------------------------------------------------------
// Output projection: Y[4096,256] = A @ W^T + b
// ---------------------------------------------------------------------------
#define GM 64
#define GN 64
#define GK 32

__global__ __launch_bounds__(256, 4) void proj_kernel(
    const float* __restrict__ W,
    const float* __restrict__ bo,
    float*       __restrict__ Y)
{
    __shared__ float As[GK][GM + 4];
    __shared__ float Ws[GK][GN + 4];

    const float* A = g_attn;
    const int tid = threadIdx.x;
    const int im0 = blockIdx.x * GM;
    const int jn0 = blockIdx.y * GN;
    const int ty = tid >> 4;
    const int tx = tid & 15;

    float acc[4][4];
#pragma unroll
    for (int r = 0; r < 4; r++)
#pragma unroll
        for (int c = 0; c < 4; c++) acc[r][c] = 0.f;

    const int lrow = tid >> 3;
    const int lc4  = (tid & 7) * 4;

    for (int k0 = 0; k0 < EE; k0 += GK) {
#pragma unroll
        for (int rr = 0; rr < 2; rr++) {
            int row = lrow + rr * 32;
            float4 v = *reinterpret_cast<const float4*>(
                A + (size_t)(im0 + row) * EE + k0 + lc4);
            As[lc4 + 0][row] = v.x;
            As[lc4 + 1][row] = v.y;
            As[lc4 + 2][row] = v.z;
            As[lc4 + 3][row] = v.w;
        }
#pragma unroll
        for (int rr = 0; rr < 2; rr++) {
            int row = lrow + rr * 32;
            float4 v = *reinterpret_cast<const float4*>(
                W + (size_t)(jn0 + row) * EE + k0 + lc4);
            Ws[lc4 + 0][row] = v.x;
            Ws[lc4 + 1][row] = v.y;
            Ws[lc4 + 2][row] = v.z;
            Ws[lc4 + 3][row] = v.w;
        }
        __syncthreads();

#pragma unroll
        for (int kk = 0; kk < GK; kk++) {
            float4 a4 = *reinterpret_cast<const float4*>(&As[kk][ty * 4]);
            float4 b4 = *reinterpret_cast<const float4*>(&Ws[kk][tx * 4]);
            acc[0][0] = fmaf(a4.x, b4.x, acc[0][0]);
            acc[0][1] = fmaf(a4.x, b4.y, acc[0][1]);
            acc[0][2] = fmaf(a4.x, b4.z, acc[0][2]);
            acc[0][3] = fmaf(a4.x, b4.w, acc[0][3]);
            acc[1][0] = fmaf(a4.y, b4.x, acc[1][0]);
            acc[1][1] = fmaf(a4.y, b4.y, acc[1][1]);
            acc[1][2] = fmaf(a4.y, b4.z, acc[1][2]);
            acc[1][3] = fmaf(a4.y, b4.w, acc[1][3]);
            acc[2][0] = fmaf(a4.z, b4.x, acc[2][0]);
            acc[2][1] = fmaf(a4.z, b4.y, acc[2][1]);
            acc[2][2] = fmaf(a4.z, b4.z, acc[2][2]);
            acc[2][3] = fmaf(a4.z, b4.w, acc[2][3]);
            acc[3][0] = fmaf(a4.w, b4.x, acc[3][0]);
            acc[3][1] = fmaf(a4.w, b4.y, acc[3][1]);
            acc[3][2] = fmaf(a4.w, b4.z, acc[3][2]);
            acc[3][3] = fmaf(a4.w, b4.w, acc[3][3]);
        }
        __syncthreads();
    }

    float4 bv = *reinterpret_cast<const float4*>(bo + jn0 + tx * 4);
#pragma unroll
    for (int r = 0; r < 4; r++) {
        int i = im0 + ty * 4 + r;
        float4 o = make_float4(acc[r][0] + bv.x, acc[r][1] + bv.y,
                               acc[r][2] + bv.z, acc[r][3] + bv.w);
        *reinterpret_cast<float4*>(Y + (size_t)i * EE + jn0 + tx * 4) = o;
    }
}

// ---------------------------------------------------------------------------
extern "C" void kernel_launch(void* const* d_in, const int* in_sizes, int n_in,
                              void* d_out, int out_size)
{
    const float* x     = (const float*)d_in[0];
    const int*   mask  = (const int*)d_in[1];
    const float* theta = (const float*)d_in[2];
    const float* W     = (const float*)d_in[3];
    const float* bo    = (const float*)d_in[4];
    float*       out   = (float*)d_out;

    prep_kernel<<<64 * 2048 / 256, 256>>>(x, theta);
    attn_kernel<<<64 * 16, 256>>>(mask);

    dim3 grid(BB * SS / GM, EE / GN);  // (64, 4)
    proj_kernel<<<grid, 256>>>(W, bo, out);
}

// round 7
// speedup vs baseline: 2.8390x; 1.1790x over previous
#include <cuda_runtime.h>
#include <cuda_fp16.h>
#include <math.h>
#include <stdint.h>

#define BB 2
#define SS 2048
#define EE 256
#define HH 32

// log2(e)/sqrt(8): fold softmax temperature + exp->exp2 into one scale.
#define CSCALE 0.51006972790221780093f

__device__ float g_attn[BB * SS * EE];   // attention output [B,S,E]
__device__ uint4 g_qh[64 * 2048];        // fp16 cos(x+theta): 8 vals (16B) per (bh,s)

__device__ __forceinline__ float ex2f(float x) {
    float r;
    asm("ex2.approx.ftz.f32 %0, %1;" : "=f"(r) : "f"(x));
    return r;
}
// Warp-level fp16 MMA, D/C fp32. Baseline sm_80 PTX -> compiles for compute_103.
__device__ __forceinline__ void mma16816(float d[4],
    uint32_t a0, uint32_t a1, uint32_t a2, uint32_t a3,
    uint32_t b0, uint32_t b1, const float c[4])
{
    asm volatile("mma.sync.aligned.m16n8k16.row.col.f32.f16.f16.f32 "
        "{%0,%1,%2,%3}, {%4,%5,%6,%7}, {%8,%9}, {%10,%11,%12,%13};"
        : "=f"(d[0]), "=f"(d[1]), "=f"(d[2]), "=f"(d[3])
        : "r"(a0), "r"(a1), "r"(a2), "r"(a3), "r"(b0), "r"(b1),
          "f"(c[0]), "f"(c[1]), "f"(c[2]), "f"(c[3]));
}

// ---------------------------------------------------------------------------
// Prep: q = cos(x + theta) -> fp16, layout [bh][s] x 16B (8 halves)
// ---------------------------------------------------------------------------
__global__ void prep_kernel(const float* __restrict__ x,
                            const float* __restrict__ theta)
{
    int idx = blockIdx.x * 256 + threadIdx.x;  // 0 .. 64*2048-1
    int bh = idx >> 11;
    int s  = idx & 2047;
    int b  = bh >> 5;
    int h  = bh & 31;
    const float* xr = x + ((size_t)b * SS + s) * EE + h * 8;
    float4 v0 = *reinterpret_cast<const float4*>(xr);
    float4 v1 = *reinterpret_cast<const float4*>(xr + 4);
    float v[8] = {v0.x, v0.y, v0.z, v0.w, v1.x, v1.y, v1.z, v1.w};
    unsigned short hs[8];
#pragma unroll
    for (int d = 0; d < 8; d++) {
        float cv = __cosf(v[d] + __ldg(theta + d));
        hs[d] = __half_as_ushort(__float2half_rn(cv));
    }
    uint4 H;
    H.x = hs[0] | (uint32_t)hs[1] << 16;  H.y = hs[2] | (uint32_t)hs[3] << 16;
    H.z = hs[4] | (uint32_t)hs[5] << 16;  H.w = hs[6] | (uint32_t)hs[7] << 16;
    g_qh[idx] = H;
}

// ---------------------------------------------------------------------------
// Warp-MMA flash attention, all-fp16 operands. CTA = (bh, 128-query tile).
// One MMA per 16q x 8k: A = [Q | e0-col], B = [K dims rows 0-7; bias row 8].
// P = exp2(S*CSCALE) -> fp16 in registers -> A-fragment of the PV MMA.
// ---------------------------------------------------------------------------
__global__ __launch_bounds__(256, 3) void attn_kernel(const int* __restrict__ mask)
{
    __shared__ uint4    sK[128];         // K tile, 16B (8 fp16) per key
    __shared__ uint32_t sBias[128];      // {fp16 bias lo, 0 hi} per key
    __shared__ uint32_t sVT[8][68];      // V^T [dim][key-pair fp16x2], padded

    const int tid  = threadIdx.x;
    const int wid  = tid >> 5;
    const int lane = tid & 31;
    const int r = lane >> 2;             // fragment row group
    const int m = lane & 3;              // fragment k group
    const int bh = blockIdx.x >> 4;
    const int qt = blockIdx.x & 15;
    const int b  = bh >> 5;

    // --- Fixed A fragment (this warp's 16 queries) ---
    const int qbase = (bh << 11) + (qt << 7) + wid * 16;
    const uint32_t* qw = reinterpret_cast<const uint32_t*>(g_qh + qbase);
    const uint32_t a0 = qw[r * 4 + m];           // row r,   dims 2m,2m+1
    const uint32_t a1 = qw[(r + 8) * 4 + m];     // row r+8
    const uint32_t a2 = (m == 0) ? 0x3C00u : 0u; // col8 = 1.0 -> picks bias row
    const uint32_t a3 = a2;

    float O[4] = {0.f, 0.f, 0.f, 0.f};   // output fragment [16q x 8d]
    float l_lo = 0.f, l_hi = 0.f;        // softmax denominators (rows r, r+8)

    const uint32_t* k32 = reinterpret_cast<const uint32_t*>(sK);

    for (int c = 0; c < 16; c++) {
        __syncthreads();                 // previous chunk's reads complete
        const int kg = (bh << 11) + (c << 7);
        if (tid < 128) {
            sK[tid] = g_qh[kg + tid];
            int mk = mask[b * SS + (c << 7) + tid];
            sBias[tid] = mk ? 0u : 0xD640u;          // fp16(-100) in low half
        } else {
            // V^T build: thread -> key pair u, dim-half hf (4 dims each)
            int u  = (tid - 128) >> 1;
            int hf = tid & 1;
            const uint32_t* ka = reinterpret_cast<const uint32_t*>(g_qh + kg + 2 * u);
            const uint32_t* kb = ka + 4;
            uint32_t ua0 = ka[hf * 2], ua1 = ka[hf * 2 + 1];
            uint32_t ub0 = kb[hf * 2], ub1 = kb[hf * 2 + 1];
            sVT[hf * 4 + 0][u] = __byte_perm(ua0, ub0, 0x5410);
            sVT[hf * 4 + 1][u] = __byte_perm(ua0, ub0, 0x7632);
            sVT[hf * 4 + 2][u] = __byte_perm(ua1, ub1, 0x5410);
            sVT[hf * 4 + 3][u] = __byte_perm(ua1, ub1, 0x7632);
        }
        __syncthreads();

        // --- S = QK^T + bias over 128 keys; exp2 + fp16 round in registers ---
        uint32_t P[16][2];
#pragma unroll
        for (int j = 0; j < 16; j++) {
            int key = 8 * j + r;
            uint32_t b0 = k32[key * 4 + m];          // K dims 2m,2m+1 (k rows 0-7)
            uint32_t b1 = (m == 0) ? sBias[key] : 0u; // k row 8 = bias
            float D[4] = {0.f, 0.f, 0.f, 0.f};
            mma16816(D, a0, a1, a2, a3, b0, b1, D);
            float p0 = ex2f(D[0] * CSCALE);
            float p1 = ex2f(D[1] * CSCALE);
            float p2 = ex2f(D[2] * CSCALE);
            float p3 = ex2f(D[3] * CSCALE);
            l_lo += p0 + p1;
            l_hi += p2 + p3;
            asm("cvt.rn.f16x2.f32 %0, %1, %2;" : "=r"(P[j][0]) : "f"(p1), "f"(p0));
            asm("cvt.rn.f16x2.f32 %0, %1, %2;" : "=r"(P[j][1]) : "f"(p3), "f"(p2));
        }

        // --- O += P * V  (8 k16 steps over 128 keys) ---
#pragma unroll
        for (int t = 0; t < 8; t++) {
            uint32_t b0 = sVT[r][t * 8 + m];          // keys 16t+2m, +1 (dim r)
            uint32_t b1 = sVT[r][t * 8 + 4 + m];      // keys 16t+8+2m, +1
            mma16816(O, P[2 * t][0], P[2 * t][1], P[2 * t + 1][0], P[2 * t + 1][1],
                     b0, b1, O);
        }
    }

    // --- Reduce denominators across the 4 threads sharing each row ---
    l_lo += __shfl_xor_sync(0xffffffffu, l_lo, 1);
    l_lo += __shfl_xor_sync(0xffffffffu, l_lo, 2);
    l_hi += __shfl_xor_sync(0xffffffffu, l_hi, 1);
    l_hi += __shfl_xor_sync(0xffffffffu, l_hi, 2);
    float inv_lo = 1.0f / l_lo;
    float inv_hi = 1.0f / l_hi;

    const int h  = bh & 31;
    const int q0 = (qt << 7) + wid * 16 + r;
    float* o1 = g_attn + ((size_t)b * SS + q0) * EE + h * 8 + 2 * m;
    float* o2 = o1 + 8 * EE;
    *reinterpret_cast<float2*>(o1) = make_float2(O[0] * inv_lo, O[1] * inv_lo);
    *reinterpret_cast<float2*>(o2) = make_float2(O[2] * inv_hi, O[3] * inv_hi);
}

// ---------------------------------------------------------------------------
// Output projection: Y[4096,256] = A @ W^T + b.  32x64 tile, 512 CTAs.
// ---------------------------------------------------------------------------
#define GM 32
#define GN 64
#define GK 32

__global__ __launch_bounds__(256, 4) void proj_kernel(
    const float* __restrict__ W,
    const float* __restrict__ bo,
    float*       __restrict__ Y)
{
    __shared__ float As[GK][GM + 4];
    __shared__ float Ws[GK][GN + 4];

    const float* A = g_attn;
    const int tid = threadIdx.x;
    const int im0 = blockIdx.x * GM;
    const int jn0 = blockIdx.y * GN;
    const int ty = tid >> 4;    // 0..15 -> rows ty*2, ty*2+1
    const int tx = tid & 15;    // cols tx*4

    float acc[2][4];
#pragma unroll
    for (int r = 0; r < 2; r++)
#pragma unroll
        for (int c = 0; c < 4; c++) acc[r][c] = 0.f;

    const int lrow = tid >> 3;        // 0..31
    const int lc4  = (tid & 7) * 4;   // k offset

    for (int k0 = 0; k0 < EE; k0 += GK) {
        // A tile: 32 rows x 32 k, one float4 per thread, transposed store
        {
            float4 v = *reinterpret_cast<const float4*>(
                A + (size_t)(im0 + lrow) * EE + k0 + lc4);
            As[lc4 + 0][lrow] = v.x;
            As[lc4 + 1][lrow] = v.y;
            As[lc4 + 2][lrow] = v.z;
            As[lc4 + 3][lrow] = v.w;
        }
        // W tile: 64 j-rows x 32 k, two float4 per thread
#pragma unroll
        for (int rr = 0; rr < 2; rr++) {
            int row = lrow + rr * 32;
            float4 v = *reinterpret_cast<const float4*>(
                W + (size_t)(jn0 + row) * EE + k0 + lc4);
            Ws[lc4 + 0][row] = v.x;
            Ws[lc4 + 1][row] = v.y;
            Ws[lc4 + 2][row] = v.z;
            Ws[lc4 + 3][row] = v.w;
        }
        __syncthreads();

#pragma unroll
        for (int kk = 0; kk < GK; kk++) {
            float2 a2 = *reinterpret_cast<const float2*>(&As[kk][ty * 2]);
            float4 b4 = *reinterpret_cast<const float4*>(&Ws[kk][tx * 4]);
            acc[0][0] = fmaf(a2.x, b4.x, acc[0][0]);
            acc[0][1] = fmaf(a2.x, b4.y, acc[0][1]);
            acc[0][2] = fmaf(a2.x, b4.z, acc[0][2]);
            acc[0][3] = fmaf(a2.x, b4.w, acc[0][3]);
            acc[1][0] = fmaf(a2.y, b4.x, acc[1][0]);
            acc[1][1] = fmaf(a2.y, b4.y, acc[1][1]);
            acc[1][2] = fmaf(a2.y, b4.z, acc[1][2]);
            acc[1][3] = fmaf(a2.y, b4.w, acc[1][3]);
        }
        __syncthreads();
    }

    float4 bv = *reinterpret_cast<const float4*>(bo + jn0 + tx * 4);
#pragma unroll
    for (int r = 0; r < 2; r++) {
        int i = im0 + ty * 2 + r;
        float4 o = make_float4(acc[r][0] + bv.x, acc[r][1] + bv.y,
                               acc[r][2] + bv.z, acc[r][3] + bv.w);
        *reinterpret_cast<float4*>(Y + (size_t)i * EE + jn0 + tx * 4) = o;
    }
}

// ---------------------------------------------------------------------------
extern "C" void kernel_launch(void* const* d_in, const int* in_sizes, int n_in,
                              void* d_out, int out_size)
{
    const float* x     = (const float*)d_in[0];
    const int*   mask  = (const int*)d_in[1];
    const float* theta = (const float*)d_in[2];
    const float* W     = (const float*)d_in[3];
    const float* bo    = (const float*)d_in[4];
    float*       out   = (float*)d_out;

    prep_kernel<<<64 * 2048 / 256, 256>>>(x, theta);
    attn_kernel<<<64 * 16, 256>>>(mask);

    dim3 grid(BB * SS / GM, EE / GN);  // (128, 4)
    proj_kernel<<<grid, 256>>>(W, bo, out);
}

// round 8
// speedup vs baseline: 4.0948x; 1.4423x over previous
#include <cuda_runtime.h>
#include <cuda_fp16.h>
#include <math.h>
#include <stdint.h>

#define BB 2
#define SS 2048
#define EE 256
#define HH 32

// log2(e)/sqrt(8): folded into the Q fragment (and the mask bias).
#define CSCALE 0.51006972790221780093f

__device__ uint32_t g_attnh[BB * SS * EE / 2];  // attention output, fp16x2 [B,S,E]
__device__ uint4 g_qh[64 * 2048];               // fp16 cos(x+theta): 8 vals (16B) per (bh,s)

__device__ __forceinline__ float ex2f(float x) {
    float r;
    asm("ex2.approx.ftz.f32 %0, %1;" : "=f"(r) : "f"(x));
    return r;
}
// Warp-level fp16 MMA, D/C fp32. Baseline sm_80 PTX -> compiles for compute_103.
__device__ __forceinline__ void mma16816(float d[4],
    uint32_t a0, uint32_t a1, uint32_t a2, uint32_t a3,
    uint32_t b0, uint32_t b1, const float c[4])
{
    asm volatile("mma.sync.aligned.m16n8k16.row.col.f32.f16.f16.f32 "
        "{%0,%1,%2,%3}, {%4,%5,%6,%7}, {%8,%9}, {%10,%11,%12,%13};"
        : "=f"(d[0]), "=f"(d[1]), "=f"(d[2]), "=f"(d[3])
        : "r"(a0), "r"(a1), "r"(a2), "r"(a3), "r"(b0), "r"(b1),
          "f"(c[0]), "f"(c[1]), "f"(c[2]), "f"(c[3]));
}

// ---------------------------------------------------------------------------
// Prep: q = cos(x + theta) -> fp16. Warp = one token row (coalesced 1KB read),
// lane = head. Block: 8 token rows.
// ---------------------------------------------------------------------------
__global__ void prep_kernel(const float* __restrict__ x,
                            const float* __restrict__ theta)
{
    const int t = threadIdx.x;
    const int b = blockIdx.x >> 8;                 // 256 blocks per batch
    const int s = ((blockIdx.x & 255) << 3) + (t >> 5);
    const int h = t & 31;
    const float* xr = x + ((size_t)b * SS + s) * EE + h * 8;
    float4 v0 = *reinterpret_cast<const float4*>(xr);
    float4 v1 = *reinterpret_cast<const float4*>(xr + 4);
    float v[8] = {v0.x, v0.y, v0.z, v0.w, v1.x, v1.y, v1.z, v1.w};
    unsigned short hs[8];
#pragma unroll
    for (int d = 0; d < 8; d++) {
        float cv = __cosf(v[d] + __ldg(theta + d));
        hs[d] = __half_as_ushort(__float2half_rn(cv));
    }
    uint4 H;
    H.x = hs[0] | (uint32_t)hs[1] << 16;  H.y = hs[2] | (uint32_t)hs[3] << 16;
    H.z = hs[4] | (uint32_t)hs[5] << 16;  H.w = hs[6] | (uint32_t)hs[7] << 16;
    g_qh[(((b << 5) + h) << 11) + s] = H;
}

// ---------------------------------------------------------------------------
// Warp-MMA flash attention, fp16 operands, double-buffered tiles.
// CTA = (bh, 128-query tile). Q pre-scaled by CSCALE; bias pre-scaled (-51).
// P = exp2(S) directly from MMA output -> fp16 A-fragment of the PV MMA.
// ---------------------------------------------------------------------------
__global__ __launch_bounds__(256, 3) void attn_kernel(const int* __restrict__ mask)
{
    __shared__ uint4    sK[2][128];      // K tile, 16B (8 fp16) per key
    __shared__ uint32_t sBias[2][128];   // {fp16 bias lo, 0 hi} per key
    __shared__ uint32_t sVT[2][8][68];   // V^T [dim][key-pair fp16x2], padded

    const int tid  = threadIdx.x;
    const int wid  = tid >> 5;
    const int lane = tid & 31;
    const int r = lane >> 2;             // fragment row group
    const int m = lane & 3;              // fragment k group
    const int bh = blockIdx.x >> 4;
    const int qt = blockIdx.x & 15;
    const int b  = bh >> 5;

    // --- Fixed A fragment: this warp's 16 queries, pre-scaled by CSCALE ---
    const int qbase = (bh << 11) + (qt << 7) + wid * 16;
    const uint32_t* qw = reinterpret_cast<const uint32_t*>(g_qh + qbase);
    uint32_t a0r = qw[r * 4 + m];                // row r,   dims 2m,2m+1
    uint32_t a1r = qw[(r + 8) * 4 + m];          // row r+8
    float2 f0 = __half22float2(*reinterpret_cast<half2*>(&a0r));
    float2 f1 = __half22float2(*reinterpret_cast<half2*>(&a1r));
    half2 s0 = __floats2half2_rn(f0.x * CSCALE, f0.y * CSCALE);
    half2 s1 = __floats2half2_rn(f1.x * CSCALE, f1.y * CSCALE);
    const uint32_t a0 = *reinterpret_cast<uint32_t*>(&s0);
    const uint32_t a1 = *reinterpret_cast<uint32_t*>(&s1);
    const uint32_t a2 = (m == 0) ? 0x3C00u : 0u; // col8 = 1.0 -> picks bias row
    const uint32_t a3 = a2;

    float O[4] = {0.f, 0.f, 0.f, 0.f};   // output fragment [16q x 8d]
    float l_lo = 0.f, l_hi = 0.f;        // softmax denominators (rows r, r+8)

    // --- Tile loader (buf selects double buffer) ---
    auto load_chunk = [&](int c, int buf) {
        const int kg = (bh << 11) + (c << 7);
        if (tid < 128) {
            sK[buf][tid] = g_qh[kg + tid];
            int mk = mask[b * SS + (c << 7) + tid];
            sBias[buf][tid] = mk ? 0u : 0xD260u;   // fp16(-51) = -100*CSCALE
        } else {
            int u  = (tid - 128) >> 1;             // key pair
            int hf = tid & 1;                      // dim half (4 dims)
            const uint32_t* ka = reinterpret_cast<const uint32_t*>(g_qh + kg + 2 * u);
            const uint32_t* kb = ka + 4;
            uint32_t ua0 = ka[hf * 2], ua1 = ka[hf * 2 + 1];
            uint32_t ub0 = kb[hf * 2], ub1 = kb[hf * 2 + 1];
            sVT[buf][hf * 4 + 0][u] = __byte_perm(ua0, ub0, 0x5410);
            sVT[buf][hf * 4 + 1][u] = __byte_perm(ua0, ub0, 0x7632);
            sVT[buf][hf * 4 + 2][u] = __byte_perm(ua1, ub1, 0x5410);
            sVT[buf][hf * 4 + 3][u] = __byte_perm(ua1, ub1, 0x7632);
        }
    };

    load_chunk(0, 0);
    __syncthreads();

    for (int c = 0; c < 16; c++) {
        const int buf = c & 1;
        if (c < 15) load_chunk(c + 1, buf ^ 1);

        const uint32_t* k32 = reinterpret_cast<const uint32_t*>(sK[buf]);

        // --- S = (Q*CSCALE)K^T + bias; exp2 + fp16 round in registers ---
        uint32_t P[16][2];
#pragma unroll
        for (int j = 0; j < 16; j++) {
            int key = 8 * j + r;
            uint32_t b0 = k32[key * 4 + m];            // K dims 2m,2m+1
            uint32_t b1 = (m == 0) ? sBias[buf][key] : 0u;
            float D[4] = {0.f, 0.f, 0.f, 0.f};
            mma16816(D, a0, a1, a2, a3, b0, b1, D);
            float p0 = ex2f(D[0]);
            float p1 = ex2f(D[1]);
            float p2 = ex2f(D[2]);
            float p3 = ex2f(D[3]);
            l_lo += p0 + p1;
            l_hi += p2 + p3;
            asm("cvt.rn.f16x2.f32 %0, %1, %2;" : "=r"(P[j][0]) : "f"(p1), "f"(p0));
            asm("cvt.rn.f16x2.f32 %0, %1, %2;" : "=r"(P[j][1]) : "f"(p3), "f"(p2));
        }

        // --- O += P * V  (8 k16 steps over 128 keys) ---
#pragma unroll
        for (int t = 0; t < 8; t++) {
            uint32_t b0 = sVT[buf][r][t * 8 + m];
            uint32_t b1 = sVT[buf][r][t * 8 + 4 + m];
            mma16816(O, P[2 * t][0], P[2 * t][1], P[2 * t + 1][0], P[2 * t + 1][1],
                     b0, b1, O);
        }
        __syncthreads();
    }

    // --- Reduce denominators across the 4 threads sharing each row ---
    l_lo += __shfl_xor_sync(0xffffffffu, l_lo, 1);
    l_lo += __shfl_xor_sync(0xffffffffu, l_lo, 2);
    l_hi += __shfl_xor_sync(0xffffffffu, l_hi, 1);
    l_hi += __shfl_xor_sync(0xffffffffu, l_hi, 2);
    float inv_lo = 1.0f / l_lo;
    float inv_hi = 1.0f / l_hi;

    const int h  = bh & 31;
    const int q0 = (qt << 7) + wid * 16 + r;
    uint32_t* op = g_attnh + ((size_t)b * SS + q0) * 128 + h * 4 + m;
    half2 o1 = __floats2half2_rn(O[0] * inv_lo, O[1] * inv_lo);
    half2 o2 = __floats2half2_rn(O[2] * inv_hi, O[3] * inv_hi);
    op[0]       = *reinterpret_cast<uint32_t*>(&o1);
    op[8 * 128] = *reinterpret_cast<uint32_t*>(&o2);
}

// ---------------------------------------------------------------------------
// Output projection via fp16 MMA: Y[4096,256] = A @ W^T + b.
// CTA: 64x64 tile, full K=256 staged once (A fp16 + W cvt to fp16).
// ---------------------------------------------------------------------------
__global__ __launch_bounds__(256, 2) void proj_kernel(
    const float* __restrict__ W,
    const float* __restrict__ bo,
    float*       __restrict__ Y)
{
    extern __shared__ uint32_t sh[];     // As: 64*132 u32, Ws: 64*132 u32
    uint32_t* As = sh;
    uint32_t* Ws = sh + 64 * 132;

    const int tid = threadIdx.x;
    const int im0 = blockIdx.x * 64;
    const int jn0 = blockIdx.y * 64;

    // Stage A (already fp16): 64 rows x 128 u32, uint4 loads
#pragma unroll
    for (int l = 0; l < 8; l++) {
        int idx = l * 256 + tid;
        int row = idx >> 5, c4 = idx & 31;
        uint4 v = *reinterpret_cast<const uint4*>(
            g_attnh + (size_t)(im0 + row) * 128 + c4 * 4);
        *reinterpret_cast<uint4*>(As + row * 132 + c4 * 4) = v;
    }
    // Stage W with fp32->fp16 conversion: 64 rows x 64 float4
#pragma unroll
    for (int l = 0; l < 16; l++) {
        int idx = l * 256 + tid;
        int row = idx >> 6, c4 = idx & 63;
        float4 v = *reinterpret_cast<const float4*>(
            W + (size_t)(jn0 + row) * 256 + c4 * 4);
        half2 h0 = __floats2half2_rn(v.x, v.y);
        half2 h1 = __floats2half2_rn(v.z, v.w);
        uint2 pk = make_uint2(*reinterpret_cast<uint32_t*>(&h0),
                              *reinterpret_cast<uint32_t*>(&h1));
        *reinterpret_cast<uint2*>(Ws + row * 132 + c4 * 2) = pk;
    }
    __syncthreads();

    const int lane = tid & 31, wid = tid >> 5;
    const int r = lane >> 2, m = lane & 3;
    const int mb  = (wid & 3) * 16;      // m-block
    const int nb0 = (wid >> 2) * 32;     // 4 n8-blocks

    float acc[4][4];
#pragma unroll
    for (int nn = 0; nn < 4; nn++)
#pragma unroll
        for (int i = 0; i < 4; i++) acc[nn][i] = 0.f;

#pragma unroll
    for (int kc = 0; kc < 16; kc++) {
        uint32_t a0 = As[(mb + r) * 132 + kc * 8 + m];
        uint32_t a1 = As[(mb + r + 8) * 132 + kc * 8 + m];
        uint32_t a2 = As[(mb + r) * 132 + kc * 8 + 4 + m];
        uint32_t a3 = As[(mb + r + 8) * 132 + kc * 8 + 4 + m];
#pragma unroll
        for (int nn = 0; nn < 4; nn++) {
            uint32_t b0 = Ws[(nb0 + nn * 8 + r) * 132 + kc * 8 + m];
            uint32_t b1 = Ws[(nb0 + nn * 8 + r) * 132 + kc * 8 + 4 + m];
            mma16816(acc[nn], a0, a1, a2, a3, b0, b1, acc[nn]);
        }
    }

    // Epilogue: bias + fp32 stores
#pragma unroll
    for (int nn = 0; nn < 4; nn++) {
        int j = jn0 + nb0 + nn * 8 + 2 * m;
        float2 bv = *reinterpret_cast<const float2*>(bo + j);
        int i0 = im0 + mb + r;
        *reinterpret_cast<float2*>(Y + (size_t)i0 * 256 + j) =
            make_float2(acc[nn][0] + bv.x, acc[nn][1] + bv.y);
        *reinterpret_cast<float2*>(Y + (size_t)(i0 + 8) * 256 + j) =
            make_float2(acc[nn][2] + bv.x, acc[nn][3] + bv.y);
    }
}

// ---------------------------------------------------------------------------
extern "C" void kernel_launch(void* const* d_in, const int* in_sizes, int n_in,
                              void* d_out, int out_size)
{
    const float* x     = (const float*)d_in[0];
    const int*   mask  = (const int*)d_in[1];
    const float* theta = (const float*)d_in[2];
    const float* W     = (const float*)d_in[3];
    const float* bo    = (const float*)d_in[4];
    float*       out   = (float*)d_out;

    prep_kernel<<<BB * SS / 8, 256>>>(x, theta);
    attn_kernel<<<64 * 16, 256>>>(mask);

    const int proj_smem = 2 * 64 * 132 * 4;   // 67.6 KB
    cudaFuncSetAttribute(proj_kernel,
                         cudaFuncAttributeMaxDynamicSharedMemorySize, proj_smem);
    dim3 grid(BB * SS / 64, EE / 64);  // (64, 4)
    proj_kernel<<<grid, 256, proj_smem>>>(W, bo, out);
}